// round 1
// baseline (speedup 1.0000x reference)
#include <cuda_runtime.h>
#include <math.h>

// Problem constants
#define Tn 128
#define Bn 2048
#define Hn 256
#define In0 18

// Tiling
#define BM 64
#define BN 64
#define KC 16
#define NTHREADS 256
#define HS_LD 68    // smem stride for activation tile (pad for bank spread, 16B aligned)
#define WS_LD 196   // smem stride for weight tile (192 gate-cols + pad)

// Ring buffers for hidden state (depth 2). Static device arrays (no alloc allowed).
__device__ float g_h1[2][Bn * Hn];
__device__ float g_h2[2][Bn * Hn];

__device__ __forceinline__ float sigf(float x) { return 1.f / (1.f + expf(-x)); }

// One accumulation stream: acc{R,Z,a3} += A[b0+..][0:K] * W[gate*Hn + j0+..][0:K]^T
// A is [*, lda] row-major activations; W is [3*Hn, ldw] row-major (PyTorch gate order r,z,n).
// a3 receives gate-n contributions (xn for the input stream, hn for the hidden stream).
__device__ __forceinline__ void stream_mm(
    const float* __restrict__ A, int lda, int K,
    const float* __restrict__ W, int ldw,
    int b0, int j0, int tid, bool vec,
    float (*hs)[HS_LD], float (*ws)[WS_LD],
    float (&aR)[16], float (&aZ)[16], float (&a3)[16])
{
    const int row = tid >> 2;   // 0..63
    const int kv  = tid & 3;    // 0..3  (covers 16 k as 4 x float4)
    const int tx  = tid & 15;
    const int ty  = tid >> 4;
    const int nch = (K + KC - 1) / KC;

    float fa[4];
    float fw[3][4];

    // ---- prefetch chunk 0 into registers ----
    {
        const int k0 = 0;
        if (vec) {
            float4 t4 = *(const float4*)(A + (size_t)(b0 + row) * lda + k0 + kv * 4);
            fa[0] = t4.x; fa[1] = t4.y; fa[2] = t4.z; fa[3] = t4.w;
            #pragma unroll
            for (int it = 0; it < 3; ++it) {
                float4 w4 = *(const float4*)(W + (size_t)(it * Hn + j0 + row) * ldw + k0 + kv * 4);
                fw[it][0] = w4.x; fw[it][1] = w4.y; fw[it][2] = w4.z; fw[it][3] = w4.w;
            }
        } else {
            #pragma unroll
            for (int i = 0; i < 4; ++i) {
                int k = k0 + kv * 4 + i;
                fa[i] = (k < K) ? A[(size_t)(b0 + row) * lda + k] : 0.f;
            }
            #pragma unroll
            for (int it = 0; it < 3; ++it)
                #pragma unroll
                for (int i = 0; i < 4; ++i) {
                    int k = k0 + kv * 4 + i;
                    fw[it][i] = (k < K) ? W[(size_t)(it * Hn + j0 + row) * ldw + k] : 0.f;
                }
        }
    }

    for (int c = 0; c < nch; ++c) {
        __syncthreads();   // previous compute (or previous stream) done with smem
        // store prefetched chunk to smem (k-major)
        #pragma unroll
        for (int i = 0; i < 4; ++i) hs[kv * 4 + i][row] = fa[i];
        #pragma unroll
        for (int it = 0; it < 3; ++it)
            #pragma unroll
            for (int i = 0; i < 4; ++i) ws[kv * 4 + i][it * 64 + row] = fw[it][i];
        __syncthreads();

        // prefetch next chunk while computing this one
        if (c + 1 < nch) {
            const int k0 = (c + 1) * KC;
            if (vec) {
                float4 t4 = *(const float4*)(A + (size_t)(b0 + row) * lda + k0 + kv * 4);
                fa[0] = t4.x; fa[1] = t4.y; fa[2] = t4.z; fa[3] = t4.w;
                #pragma unroll
                for (int it = 0; it < 3; ++it) {
                    float4 w4 = *(const float4*)(W + (size_t)(it * Hn + j0 + row) * ldw + k0 + kv * 4);
                    fw[it][0] = w4.x; fw[it][1] = w4.y; fw[it][2] = w4.z; fw[it][3] = w4.w;
                }
            } else {
                #pragma unroll
                for (int i = 0; i < 4; ++i) {
                    int k = k0 + kv * 4 + i;
                    fa[i] = (k < K) ? A[(size_t)(b0 + row) * lda + k] : 0.f;
                }
                #pragma unroll
                for (int it = 0; it < 3; ++it)
                    #pragma unroll
                    for (int i = 0; i < 4; ++i) {
                        int k = k0 + kv * 4 + i;
                        fw[it][i] = (k < K) ? W[(size_t)(it * Hn + j0 + row) * ldw + k] : 0.f;
                    }
            }
        }

        // FMA core: 16 k x (4 batch x 4 unit) x 3 gates
        #pragma unroll
        for (int k = 0; k < KC; ++k) {
            const float4 hb = *(const float4*)&hs[k][ty * 4];
            const float4 w0 = *(const float4*)&ws[k][tx * 4];
            const float4 w1 = *(const float4*)&ws[k][64 + tx * 4];
            const float4 w2 = *(const float4*)&ws[k][128 + tx * 4];
            float hv[4] = {hb.x, hb.y, hb.z, hb.w};
            float wr[4] = {w0.x, w0.y, w0.z, w0.w};
            float wz[4] = {w1.x, w1.y, w1.z, w1.w};
            float wn[4] = {w2.x, w2.y, w2.z, w2.w};
            #pragma unroll
            for (int ii = 0; ii < 4; ++ii)
                #pragma unroll
                for (int jj = 0; jj < 4; ++jj) {
                    aR[ii * 4 + jj] = fmaf(hv[ii], wr[jj], aR[ii * 4 + jj]);
                    aZ[ii * 4 + jj] = fmaf(hv[ii], wz[jj], aZ[ii * 4 + jj]);
                    a3[ii * 4 + jj] = fmaf(hv[ii], wn[jj], a3[ii * 4 + jj]);
                }
        }
    }
}

// Pipelined super-step l: CTAs [0,128) run layer0 at t=l, CTAs [128,256) run layer1 at t=l-1.
__global__ void __launch_bounds__(NTHREADS, 2)
gru_step_kernel(const float* __restrict__ x,
                const float* __restrict__ Wih0, const float* __restrict__ Whh0,
                const float* __restrict__ bih0, const float* __restrict__ bhh0,
                const float* __restrict__ Wih1, const float* __restrict__ Whh1,
                const float* __restrict__ bih1, const float* __restrict__ bhh1,
                int l)
{
    __shared__ float hs[KC][HS_LD];
    __shared__ float ws[KC][WS_LD];

    const int cta = blockIdx.x;
    const bool L1 = (cta >= 128);
    const int t = L1 ? (l - 1) : l;
    if (t < 0 || t >= Tn) return;

    const int bx = cta & 127;
    const int b0 = (bx >> 2) * BM;   // batch tile
    const int j0 = (bx & 3) * BN;    // unit tile
    const int tid = threadIdx.x;

    const float *xin, *Wih, *bih, *Whh, *bhh, *hprev;
    float* hout;
    int In;
    bool vecx;
    if (!L1) {
        xin = x + (size_t)t * Bn * In0; In = In0; vecx = false;
        Wih = Wih0; bih = bih0; Whh = Whh0; bhh = bhh0;
        hprev = g_h1[(t + 1) & 1];
        hout  = g_h1[t & 1];
    } else {
        xin = g_h1[t & 1]; In = Hn; vecx = true;   // h1[t] written by previous launch
        Wih = Wih1; bih = bih1; Whh = Whh1; bhh = bhh1;
        hprev = g_h2[(t + 1) & 1];
        hout  = g_h2[t & 1];
    }

    float aR[16], aZ[16], aXN[16], aHN[16];
    #pragma unroll
    for (int o = 0; o < 16; ++o) { aR[o] = 0.f; aZ[o] = 0.f; aXN[o] = 0.f; aHN[o] = 0.f; }

    // input stream: x @ W_ih^T  -> (r, z, xn)
    stream_mm(xin, In, In, Wih, In, b0, j0, tid, vecx, hs, ws, aR, aZ, aXN);
    // hidden stream: h @ W_hh^T -> (r, z, hn)
    stream_mm(hprev, Hn, Hn, Whh, Hn, b0, j0, tid, true, hs, ws, aR, aZ, aHN);

    const int tx = tid & 15, ty = tid >> 4;
    #pragma unroll
    for (int jj = 0; jj < 4; ++jj) {
        const int j = j0 + tx * 4 + jj;
        const float br = bih[j]          + bhh[j];
        const float bz = bih[Hn + j]     + bhh[Hn + j];
        const float bin_ = bih[2 * Hn + j];
        const float bhn  = bhh[2 * Hn + j];
        #pragma unroll
        for (int ii = 0; ii < 4; ++ii) {
            const int b = b0 + ty * 4 + ii;
            const int o = ii * 4 + jj;
            const float r = sigf(aR[o] + br);
            const float z = sigf(aZ[o] + bz);
            const float n = tanhf(aXN[o] + bin_ + r * (aHN[o] + bhn));
            const float hp = hprev[(size_t)b * Hn + j];
            hout[(size_t)b * Hn + j] = (1.f - z) * n + z * hp;
        }
    }
}

// Final FC + sigmoid*2-1 on h2[T-1]. One warp per batch row.
__global__ void fc_kernel(const float* __restrict__ fcw, const float* __restrict__ fcb,
                          float* __restrict__ out)
{
    const int warp = (blockIdx.x * blockDim.x + threadIdx.x) >> 5;
    const int lane = threadIdx.x & 31;
    if (warp >= Bn) return;
    const float* h = g_h2[(Tn - 1) & 1] + (size_t)warp * Hn;
    float a0 = 0.f, a1 = 0.f, a2 = 0.f, a3 = 0.f;
    for (int k = lane; k < Hn; k += 32) {
        const float hv = h[k];
        a0 = fmaf(hv, fcw[k], a0);
        a1 = fmaf(hv, fcw[Hn + k], a1);
        a2 = fmaf(hv, fcw[2 * Hn + k], a2);
        a3 = fmaf(hv, fcw[3 * Hn + k], a3);
    }
    #pragma unroll
    for (int s = 16; s; s >>= 1) {
        a0 += __shfl_xor_sync(0xFFFFFFFFu, a0, s);
        a1 += __shfl_xor_sync(0xFFFFFFFFu, a1, s);
        a2 += __shfl_xor_sync(0xFFFFFFFFu, a2, s);
        a3 += __shfl_xor_sync(0xFFFFFFFFu, a3, s);
    }
    if (lane == 0) {
        out[warp * 4 + 0] = 2.f * sigf(a0 + fcb[0]) - 1.f;
        out[warp * 4 + 1] = 2.f * sigf(a1 + fcb[1]) - 1.f;
        out[warp * 4 + 2] = 2.f * sigf(a2 + fcb[2]) - 1.f;
        out[warp * 4 + 3] = 2.f * sigf(a3 + fcb[3]) - 1.f;
    }
}

extern "C" void kernel_launch(void* const* d_in, const int* in_sizes, int n_in,
                              void* d_out, int out_size)
{
    const float* x    = (const float*)d_in[0];
    const float* Wih0 = (const float*)d_in[1];
    const float* Whh0 = (const float*)d_in[2];
    const float* bih0 = (const float*)d_in[3];
    const float* bhh0 = (const float*)d_in[4];
    const float* Wih1 = (const float*)d_in[5];
    const float* Whh1 = (const float*)d_in[6];
    const float* bih1 = (const float*)d_in[7];
    const float* bhh1 = (const float*)d_in[8];
    const float* fcw  = (const float*)d_in[9];
    const float* fcb  = (const float*)d_in[10];
    float* out = (float*)d_out;
    (void)in_sizes; (void)n_in; (void)out_size;

    // zero the "previous state" ring slots used at t=0 (slot (0+1)&1 == 1)
    void *p1 = nullptr, *p2 = nullptr;
    cudaGetSymbolAddress(&p1, g_h1);
    cudaGetSymbolAddress(&p2, g_h2);
    cudaMemsetAsync((char*)p1 + sizeof(float) * (size_t)Bn * Hn, 0,
                    sizeof(float) * (size_t)Bn * Hn, 0);
    cudaMemsetAsync((char*)p2 + sizeof(float) * (size_t)Bn * Hn, 0,
                    sizeof(float) * (size_t)Bn * Hn, 0);

    // 129 pipelined super-steps: layer0 computes t=l, layer1 computes t=l-1
    for (int l = 0; l <= Tn; ++l) {
        gru_step_kernel<<<256, NTHREADS>>>(x, Wih0, Whh0, bih0, bhh0,
                                           Wih1, Whh1, bih1, bhh1, l);
    }

    fc_kernel<<<(Bn * 32) / 256, 256>>>(fcw, fcb, out);
}